// round 17
// baseline (speedup 1.0000x reference)
#include <cuda_runtime.h>
#include <math.h>
#include <stdint.h>

#define Bc   4
#define Gc   16906
#define Dc   256
#define DHc  32
#define Mc   110
#define Lc   6
#define FFc  1024
#define Sc   8
#define Rc   (Bc*Sc)           // 32 state rows
#define NB   32                // persistent blocks
#define NT   256

#define XN_SCALE   0.42044820762685725f   // 32^-0.25
#define M_RSQRT    0.09534625892455922f   // 110^-0.5
#define FEPS       1e-4f

// ---------------- device scratch ----------------
__device__ __align__(128) float g_e[Bc*Gc];
__device__ float    g_part[Bc*8];
__device__ unsigned g_umax;
__device__ unsigned g_ustab[Lc];
__device__ int      g_cnt[Rc];
__device__ __align__(128) float g_sx[Rc*Dc];
__device__ __align__(128) float g_sq[Rc*Dc];
__device__ __align__(128) float g_sk[Rc*Dc];
__device__ __align__(128) float g_sv[Rc*Dc];
__device__ __align__(128) float g_so[Rc*Dc];
__device__ __align__(128) float g_sff[Rc*FFc];
__device__ int          g_bar_count = 0;
__device__ volatile int g_bar_gen   = 0;

__device__ __forceinline__ unsigned fflip(float f){
    unsigned u = __float_as_uint(f);
    return (u & 0x80000000u) ? ~u : (u | 0x80000000u);
}
__device__ __forceinline__ float funflip(unsigned u){
    unsigned b = (u & 0x80000000u) ? (u ^ 0x80000000u) : ~u;
    return __uint_as_float(b);
}
__device__ __forceinline__ float gelu_exact(float x){
    return 0.5f*x*(1.0f + erff(x*0.7071067811865476f));
}

__device__ __forceinline__ void gridbar(){
    __syncthreads();
    if(threadIdx.x==0){
        int gen = g_bar_gen;
        __threadfence();
        if(atomicAdd(&g_bar_count, 1) == NB-1){
            g_bar_count = 0;
            __threadfence();
            g_bar_gen = gen + 1;
        } else {
            while(g_bar_gen == gen) { }
            __threadfence();
        }
    }
    __syncthreads();
}

__global__ __launch_bounds__(NT)
void forward_kernel(const float* __restrict__ expr, const float* __restrict__ temb,
                    const float* __restrict__ cls,
                    const float* __restrict__ ln1_g, const float* __restrict__ ln1_b,
                    const float* __restrict__ wq, const float* __restrict__ bq,
                    const float* __restrict__ wk, const float* __restrict__ bk,
                    const float* __restrict__ wv, const float* __restrict__ bv,
                    const float* __restrict__ wo, const float* __restrict__ bo,
                    const float* __restrict__ ln2_g, const float* __restrict__ ln2_b,
                    const float* __restrict__ w1, const float* __restrict__ b1,
                    const float* __restrict__ w2, const float* __restrict__ b2,
                    const float* __restrict__ pw, const float* __restrict__ pb,
                    const float* __restrict__ projs,
                    float* __restrict__ out)
{
    __shared__ union {
        float x[Rc][Dc];                                   // row buffer for M=32 GEMMs (32KB)
        struct {
            float sp[Mc*DHc];
            float xk[Sc][DHc], xq[Sc][DHc], xv[Sc][DHc];
            float kf[Sc][112], qf[Sc][112];
            float sctx[Mc*DHc];
            float sksum[112];
            float sden[Sc], dgk[Sc], dgq[Sc], scnt[Sc];
        } a;
    } su;
    __shared__ float sred[NT];
    __shared__ float smu[Rc], srstd[Rc];
    __shared__ int   shist32[Rc];

    const int tid  = threadIdx.x;
    const int bid  = blockIdx.x;
    const int warp = tid>>5, lane = tid&31;
    const int gidx0 = bid*NT + tid;

    // ---------- S0: reset + partial rowsums (32 blocks: b = bid>>3, slice = bid&7) ----------
    if(bid == 0 && tid == 0){
        g_umax = 0u;
        for(int l=0;l<Lc;l++) g_ustab[l] = 0u;
    }
    if(bid == 0 && tid < Rc) g_cnt[tid] = ((tid&7)==7) ? 1 : 0;
    {
        int b = bid>>3, slice = bid&7;
        int start = slice*2114;
        int end = start+2114 < Gc ? start+2114 : Gc;
        float s = 0.f;
        for(int i=start+tid; i<end; i+=NT) s += fabsf(expr[(size_t)b*Gc+i]);
        sred[tid]=s; __syncthreads();
        for(int st=128; st; st>>=1){ if(tid<st) sred[tid]+=sred[tid+st]; __syncthreads(); }
        if(tid==0) g_part[b*8+slice]=sred[0];
    }
    gridbar();

    // ---------- S1: e + global max ----------
    {
        float den[Bc];
        #pragma unroll
        for(int b=0;b<Bc;b++){
            float s=0.f;
            #pragma unroll
            for(int j=0;j<8;j++) s += g_part[b*8+j];
            den[b] = fmaxf(s, 1e-12f);
        }
        float lmax = 0.f;
        for(int i = gidx0; i < Bc*Gc; i += NB*NT){
            int b = i / Gc;
            float e = log1pf(expr[i]/den[b]*1e4f);
            g_e[i] = e;
            lmax = fmaxf(lmax, e);
        }
        sred[tid]=lmax; __syncthreads();
        for(int st=128; st; st>>=1){ if(tid<st) sred[tid]=fmaxf(sred[tid],sred[tid+st]); __syncthreads(); }
        if(tid==0) atomicMax(&g_umax, fflip(sred[0]));
    }
    gridbar();

    // ---------- S2: histogram + seed states ----------
    if(tid < Rc) shist32[tid] = 0;
    __syncthreads();
    {
        float maxe = funflip(g_umax);
        float step = maxe/7.0f;
        for(int i = gidx0; i < Bc*Gc; i += NB*NT){
            int b = i / Gc;
            float e = g_e[i];
            int t = (0.0f < e) ? 1 : 0;
            #pragma unroll
            for(int j=1;j<7;j++) t += ((float)j*step < e) ? 1 : 0;
            if(t>6) t=6;
            atomicAdd(&shist32[b*8+t], 1);
        }
    }
    __syncthreads();
    if(tid < Rc && shist32[tid] != 0) atomicAdd(&g_cnt[tid], shist32[tid]);
    {   // seed: Rc*Dc = 8192 = NB*NT exactly
        int i = gidx0;
        int r = i >> 8, d = i & 255;
        int s = r & 7;
        g_sx[i] = (s==7) ? cls[d] : temb[s*Dc + d];
    }
    gridbar();

    // ---------- layers ----------
    for(int l=0; l<Lc; l++){
        const float* wq_l = wq + (size_t)l*Dc*Dc;  const float* bq_l = bq + l*Dc;
        const float* wk_l = wk + (size_t)l*Dc*Dc;  const float* bk_l = bk + l*Dc;
        const float* wv_l = wv + (size_t)l*Dc*Dc;  const float* bv_l = bv + l*Dc;
        const float* wo_l = wo + (size_t)l*Dc*Dc;  const float* bo_l = bo + l*Dc;
        const float* w1_l = w1 + (size_t)l*Dc*FFc; const float* b1_l = b1 + l*FFc;
        const float* w2_l = w2 + (size_t)l*FFc*Dc; const float* b2_l = b2 + l*Dc;
        const float* pr_l = projs + (size_t)l*Mc*DHc;
        const float* lg1 = ln1_g + l*Dc, *lb1 = ln1_b + l*Dc;
        const float* lg2 = ln2_g + l*Dc, *lb2 = ln2_b + l*Dc;

        // -- QKV: 24 blocks; block = (w, colchunk of 32); LN1 computed in-block --
        if(bid < 24){
            int w = bid>>3, cc = bid&7;
            for(int i=tid;i<Rc*Dc;i+=NT) su.x[0][i] = g_sx[i];
            __syncthreads();
            #pragma unroll
            for(int j=0;j<4;j++){
                int r = warp*4+j;
                float s=0.f;
                #pragma unroll
                for(int q=0;q<8;q++) s += su.x[r][lane+32*q];
                #pragma unroll
                for(int o=16;o;o>>=1) s += __shfl_xor_sync(0xffffffffu,s,o);
                float mu = s*(1.f/256.f);
                float v=0.f;
                #pragma unroll
                for(int q=0;q<8;q++){ float d = su.x[r][lane+32*q]-mu; v += d*d; }
                #pragma unroll
                for(int o=16;o;o>>=1) v += __shfl_xor_sync(0xffffffffu,v,o);
                if(lane==0){ smu[r]=mu; srstd[r]=rsqrtf(v*(1.f/256.f)+1e-5f); }
            }
            __syncthreads();
            for(int i=tid;i<Rc*Dc;i+=NT){
                int r=i>>8, k=i&255;
                su.x[r][k] = (su.x[r][k]-smu[r])*srstd[r]*lg1[k]+lb1[k];
            }
            __syncthreads();
            const float* W  = (w==0)?wq_l:((w==1)?wk_l:wv_l);
            const float* bb = (w==0)?bq_l:((w==1)?bk_l:bv_l);
            float* Y        = (w==0)?g_sq:((w==1)?g_sk:g_sv);
            int gc = cc*32 + lane;
            int r0 = warp*4;
            float a0=0,a1=0,a2=0,a3=0;
            #pragma unroll 4
            for(int k=0;k<Dc;k++){
                float wv = W[(size_t)k*Dc + gc];
                a0 += su.x[r0  ][k]*wv;
                a1 += su.x[r0+1][k]*wv;
                a2 += su.x[r0+2][k]*wv;
                a3 += su.x[r0+3][k]*wv;
            }
            float bbv = bb[gc];
            Y[(size_t)(r0  )*Dc+gc]=a0+bbv;
            Y[(size_t)(r0+1)*Dc+gc]=a1+bbv;
            Y[(size_t)(r0+2)*Dc+gc]=a2+bbv;
            Y[(size_t)(r0+3)*Dc+gc]=a3+bbv;
        }
        gridbar();

        // -- attention part A: raw dd + stabilizer max (blocks 0..31) --
        {
            int b = bid>>3, h = bid&7;
            for(int i=tid;i<Mc*DHc;i+=NT) su.a.sp[i]=pr_l[i];
            { size_t off = (size_t)(b*8+warp)*Dc + h*DHc + lane;
              su.a.xk[warp][lane]=g_sk[off]*XN_SCALE;
              su.a.xq[warp][lane]=g_sq[off]*XN_SCALE;
              su.a.xv[warp][lane]=g_sv[off]; }
            if(tid<Sc) su.a.scnt[tid] = (float)g_cnt[b*8+tid];
            __syncthreads();
            {
                float kk = su.a.xk[warp][lane]*su.a.xk[warp][lane];
                float qq = su.a.xq[warp][lane]*su.a.xq[warp][lane];
                #pragma unroll
                for(int o=16;o;o>>=1){ kk += __shfl_xor_sync(0xffffffffu,kk,o); qq += __shfl_xor_sync(0xffffffffu,qq,o); }
                if(lane==0){ su.a.dgk[warp]=0.5f*kk; su.a.dgq[warp]=0.5f*qq; }
            }
            __syncthreads();
            float mx = -3.4e38f;
            for(int i=tid;i<Sc*Mc;i+=NT){
                int s=i/Mc, m=i%Mc;
                float ddk=0.f, ddq=0.f;
                #pragma unroll
                for(int dd=0;dd<DHc;dd++){ ddk += su.a.xk[s][dd]*su.a.sp[m*DHc+dd]; ddq += su.a.xq[s][dd]*su.a.sp[m*DHc+dd]; }
                su.a.kf[s][m] = ddk;
                su.a.qf[s][m] = ddq;
                if(su.a.scnt[s] > 0.f) mx = fmaxf(mx, ddk);
            }
            sred[tid]=mx; __syncthreads();
            for(int st=128; st; st>>=1){ if(tid<st) sred[tid]=fmaxf(sred[tid],sred[tid+st]); __syncthreads(); }
            if(tid==0) atomicMax(&g_ustab[l], fflip(sred[0]));
        }
        gridbar();

        // -- attention part B (smem persisted across barrier) --
        {
            int b = bid>>3, h = bid&7;
            float stab = funflip(g_ustab[l]);
            for(int i=tid;i<Sc*Mc;i+=NT){
                int s=i/Mc, m=i%Mc;
                su.a.kf[s][m] = M_RSQRT*(expf(su.a.kf[s][m] - su.a.dgk[s] - stab) + FEPS);
            }
            __syncthreads();
            {
                float mxq=-3.4e38f;
                for(int m=lane;m<Mc;m+=32) mxq=fmaxf(mxq, su.a.qf[warp][m]);
                #pragma unroll
                for(int o=16;o;o>>=1) mxq=fmaxf(mxq,__shfl_xor_sync(0xffffffffu,mxq,o));
                for(int m=lane;m<Mc;m+=32)
                    su.a.qf[warp][m] = M_RSQRT*(expf(su.a.qf[warp][m]-su.a.dgq[warp]-mxq) + FEPS);
            }
            __syncthreads();
            for(int i=tid;i<Mc*DHc;i+=NT){
                int m=i>>5, d=i&31;
                float a=0.f;
                #pragma unroll
                for(int s=0;s<Sc;s++) a += su.a.scnt[s]*su.a.kf[s][m]*su.a.xv[s][d];
                su.a.sctx[i]=a;
            }
            for(int m=tid;m<Mc;m+=NT){
                float a=0.f;
                #pragma unroll
                for(int s=0;s<Sc;s++) a += su.a.scnt[s]*su.a.kf[s][m];
                su.a.sksum[m]=a;
            }
            __syncthreads();
            {
                float a=0.f;
                for(int m=lane;m<Mc;m+=32) a += su.a.qf[warp][m]*su.a.sksum[m];
                #pragma unroll
                for(int o=16;o;o>>=1) a += __shfl_xor_sync(0xffffffffu,a,o);
                if(lane==0) su.a.sden[warp]=a;
            }
            __syncthreads();
            {
                float a=0.f;
                for(int m=0;m<Mc;m++) a += su.a.qf[warp][m]*su.a.sctx[m*DHc+lane];
                g_so[(size_t)(b*8+warp)*Dc + h*DHc + lane] = a/su.a.sden[warp];
            }
        }
        gridbar();

        // -- Wo + residual: 8 blocks, 32-col chunks --
        if(bid < 8){
            for(int i=tid;i<Rc*Dc;i+=NT) su.x[0][i] = g_so[i];
            __syncthreads();
            int gc = bid*32 + lane;
            int r0 = warp*4;
            float a0=0,a1=0,a2=0,a3=0;
            #pragma unroll 4
            for(int k=0;k<Dc;k++){
                float wv = wo_l[(size_t)k*Dc + gc];
                a0 += su.x[r0  ][k]*wv;
                a1 += su.x[r0+1][k]*wv;
                a2 += su.x[r0+2][k]*wv;
                a3 += su.x[r0+3][k]*wv;
            }
            float bbv = bo_l[gc];
            g_sx[(size_t)(r0  )*Dc+gc] += a0+bbv;
            g_sx[(size_t)(r0+1)*Dc+gc] += a1+bbv;
            g_sx[(size_t)(r0+2)*Dc+gc] += a2+bbv;
            g_sx[(size_t)(r0+3)*Dc+gc] += a3+bbv;
        }
        gridbar();

        // -- FFN1: 32 blocks, 32-col chunks of 1024; LN2 in-block + GELU --
        {
            for(int i=tid;i<Rc*Dc;i+=NT) su.x[0][i] = g_sx[i];
            __syncthreads();
            #pragma unroll
            for(int j=0;j<4;j++){
                int r = warp*4+j;
                float s=0.f;
                #pragma unroll
                for(int q=0;q<8;q++) s += su.x[r][lane+32*q];
                #pragma unroll
                for(int o=16;o;o>>=1) s += __shfl_xor_sync(0xffffffffu,s,o);
                float mu = s*(1.f/256.f);
                float v=0.f;
                #pragma unroll
                for(int q=0;q<8;q++){ float d = su.x[r][lane+32*q]-mu; v += d*d; }
                #pragma unroll
                for(int o=16;o;o>>=1) v += __shfl_xor_sync(0xffffffffu,v,o);
                if(lane==0){ smu[r]=mu; srstd[r]=rsqrtf(v*(1.f/256.f)+1e-5f); }
            }
            __syncthreads();
            for(int i=tid;i<Rc*Dc;i+=NT){
                int r=i>>8, k=i&255;
                su.x[r][k] = (su.x[r][k]-smu[r])*srstd[r]*lg2[k]+lb2[k];
            }
            __syncthreads();
            int gc = bid*32 + lane;
            int r0 = warp*4;
            float a0=0,a1=0,a2=0,a3=0;
            #pragma unroll 4
            for(int k=0;k<Dc;k++){
                float wv = w1_l[(size_t)k*FFc + gc];
                a0 += su.x[r0  ][k]*wv;
                a1 += su.x[r0+1][k]*wv;
                a2 += su.x[r0+2][k]*wv;
                a3 += su.x[r0+3][k]*wv;
            }
            float bbv = b1_l[gc];
            g_sff[(size_t)(r0  )*FFc+gc]=gelu_exact(a0+bbv);
            g_sff[(size_t)(r0+1)*FFc+gc]=gelu_exact(a1+bbv);
            g_sff[(size_t)(r0+2)*FFc+gc]=gelu_exact(a2+bbv);
            g_sff[(size_t)(r0+3)*FFc+gc]=gelu_exact(a3+bbv);
        }
        gridbar();

        // -- FFN2 + residual: 8 blocks, K=1024, sff read from global (warp-broadcast) --
        if(bid < 8){
            int gc = bid*32 + lane;
            int r0 = warp*4;
            float a0=0,a1=0,a2=0,a3=0;
            const float* f0 = g_sff + (size_t)(r0  )*FFc;
            const float* f1 = g_sff + (size_t)(r0+1)*FFc;
            const float* f2 = g_sff + (size_t)(r0+2)*FFc;
            const float* f3 = g_sff + (size_t)(r0+3)*FFc;
            #pragma unroll 4
            for(int k=0;k<FFc;k++){
                float wv = w2_l[(size_t)k*Dc + gc];
                a0 += f0[k]*wv;
                a1 += f1[k]*wv;
                a2 += f2[k]*wv;
                a3 += f3[k]*wv;
            }
            float bbv = b2_l[gc];
            g_sx[(size_t)(r0  )*Dc+gc] += a0+bbv;
            g_sx[(size_t)(r0+1)*Dc+gc] += a1+bbv;
            g_sx[(size_t)(r0+2)*Dc+gc] += a2+bbv;
            g_sx[(size_t)(r0+3)*Dc+gc] += a3+bbv;
        }
        gridbar();
    }

    // ---------- final projection (cls rows): 4 blocks ----------
    if(bid < Bc){
        int b = bid;
        const float* xp = g_sx + (size_t)(b*8+7)*Dc;
        float a0=0,a1=0,a2=0,a3=0;
        const float* wp = pw + tid;
        #pragma unroll 8
        for(int k=0;k<Dc;k+=4){
            a0 += xp[k  ]*wp[(size_t)k*Dc];
            a1 += xp[k+1]*wp[(size_t)(k+1)*Dc];
            a2 += xp[k+2]*wp[(size_t)(k+2)*Dc];
            a3 += xp[k+3]*wp[(size_t)(k+3)*Dc];
        }
        out[b*Dc + tid] = (a0+a1)+(a2+a3) + pb[tid];
    }
}

// ---------------- launch ----------------
extern "C" void kernel_launch(void* const* d_in, const int* in_sizes, int n_in,
                              void* d_out, int out_size){
    const float* expr      = (const float*)d_in[0];
    const float* token_emb = (const float*)d_in[1];
    const float* cls_token = (const float*)d_in[2];
    const float* ln1_g     = (const float*)d_in[3];
    const float* ln1_b     = (const float*)d_in[4];
    const float* wq        = (const float*)d_in[5];
    const float* bq        = (const float*)d_in[6];
    const float* wk        = (const float*)d_in[7];
    const float* bk        = (const float*)d_in[8];
    const float* wv        = (const float*)d_in[9];
    const float* bv        = (const float*)d_in[10];
    const float* wo        = (const float*)d_in[11];
    const float* bo        = (const float*)d_in[12];
    const float* ln2_g     = (const float*)d_in[13];
    const float* ln2_b     = (const float*)d_in[14];
    const float* w1        = (const float*)d_in[15];
    const float* b1        = (const float*)d_in[16];
    const float* w2        = (const float*)d_in[17];
    const float* b2        = (const float*)d_in[18];
    const float* proj_w    = (const float*)d_in[19];
    const float* proj_b    = (const float*)d_in[20];
    const float* projs     = (const float*)d_in[21];
    float* out = (float*)d_out;

    forward_kernel<<<NB, NT>>>(expr, token_emb, cls_token,
                               ln1_g, ln1_b, wq, bq, wk, bk, wv, bv, wo, bo,
                               ln2_g, ln2_b, w1, b1, w2, b2,
                               proj_w, proj_b, projs, out);
}